// round 1
// baseline (speedup 1.0000x reference)
#include <cuda_runtime.h>
#include <math.h>

// Problem constants
#define Bq   64
#define Tq   128
#define Eq   300
#define Hq   512
#define Cq   256
#define Mq   512
#define RPS  (Bq*Tq)      // rows per sequence: 8192
#define NROWS (2*RPS)     // 16384
#define G4H  (4*Hq)       // 2048
#define D2H  (2*Hq)       // 1024

// -------- scratch (static device globals; no allocation in kernel_launch) ----
__device__ float d_xW[2][NROWS][G4H];   // [dir][(seq*B+b)*T+t][4H]  (~268 MB)
__device__ float d_Hout[NROWS][D2H];    // bi-LSTM outputs             (64 MB)
__device__ float d_P[NROWS][Cq];        // attention pre-activations   (16 MB)
__device__ float d_hbuf[2][4][Bq][Hq];  // ping-pong hidden state
__device__ float d_cbuf[4][Bq][Hq];     // cell state
__device__ float d_r[2][Bq][D2H];       // pooled representations

// rec: 0=s1 fwd, 1=s2 fwd, 2=s1 bwd, 3=s2 bwd  (seq = rec&1, dir = rec>>1)

__global__ void init_state(const float* s1_h0, const float* s1_c0,
                           const float* s2_h0, const float* s2_c0) {
    int idx = blockIdx.x * blockDim.x + threadIdx.x;
    if (idx >= 4 * Bq * Hq) return;
    int j = idx % Hq;
    int b = (idx / Hq) % Bq;
    int rec = idx / (Hq * Bq);
    int seq = rec & 1, dir = rec >> 1;
    const float* h0 = seq ? s2_h0 : s1_h0;
    const float* c0 = seq ? s2_c0 : s1_c0;
    d_hbuf[0][rec][b][j] = h0[(dir * Bq + b) * Hq + j];
    d_cbuf[rec][b][j]    = c0[(dir * Bq + b) * Hq + j];
}

// ---------------- xW GEMM with fused embedding gather -----------------------
// C[16384, 2048] = emb[tok[row]] (16384 x 300) @ Wih^T (300 x 2048) + bias
__global__ __launch_bounds__(256)
void xw_gemm(const int* __restrict__ s1, const int* __restrict__ s2,
             const float* __restrict__ emb, const float* __restrict__ Wih,
             const float* __restrict__ bias, int dir) {
    __shared__ float sA[64][17];
    __shared__ float sB[64][17];
    __shared__ int   stok[64];
    int tx = threadIdx.x & 15, ty = threadIdx.x >> 4;
    int n0 = blockIdx.x * 64, m0 = blockIdx.y * 64;

    if (threadIdx.x < 64) {
        int m = m0 + threadIdx.x;
        stok[threadIdx.x] = (m < RPS) ? s1[m] : s2[m - RPS];
    }
    float acc[4][4] = {};
    __syncthreads();

    for (int kt = 0; kt < (Eq + 15) / 16; ++kt) {
        int k0 = kt * 16;
#pragma unroll
        for (int i = 0; i < 4; ++i) {
            int e = threadIdx.x + i * 256;
            int r = e >> 4, k = e & 15;
            int kk = k0 + k;
            sA[r][k] = (kk < Eq) ? emb[(long)stok[r] * Eq + kk] : 0.f;
            sB[r][k] = (kk < Eq) ? Wih[(long)(n0 + r) * Eq + kk] : 0.f;
        }
        __syncthreads();
#pragma unroll
        for (int k = 0; k < 16; ++k) {
            float a[4], bb[4];
#pragma unroll
            for (int i = 0; i < 4; ++i) a[i] = sA[ty * 4 + i][k];
#pragma unroll
            for (int j = 0; j < 4; ++j) bb[j] = sB[tx * 4 + j][k];
#pragma unroll
            for (int i = 0; i < 4; ++i)
#pragma unroll
                for (int j = 0; j < 4; ++j) acc[i][j] += a[i] * bb[j];
        }
        __syncthreads();
    }
#pragma unroll
    for (int i = 0; i < 4; ++i)
#pragma unroll
        for (int j = 0; j < 4; ++j) {
            int m = m0 + ty * 4 + i, n = n0 + tx * 4 + j;
            d_xW[dir][m][n] = acc[i][j] + bias[n];
        }
}

// ---------------- fused LSTM step: g = xW + h@Whh^T, gate, update -----------
// grid: (16 col-chunks of 32 H-cols, 8 row-blocks of 32 batch rows); 256 thr.
// Each thread: 4 batch rows x (4 gates of one H-column).
__global__ __launch_bounds__(256)
void lstm_step(int t, int cur,
               const int* __restrict__ s1_len, const int* __restrict__ s2_len,
               const float* __restrict__ Whh_f, const float* __restrict__ Whh_b) {
    __shared__ float sH[32][17];
    __shared__ float sW[128][17];
    int tx = threadIdx.x & 31;   // H-column within chunk
    int ty = threadIdx.x >> 5;   // 0..7, 4 rows each
    int rb  = blockIdx.y;
    int rec = rb >> 1;
    int b0  = (rb & 1) * 32;
    int j0  = blockIdx.x * 32;
    int seq = rec & 1, dir = rec >> 1;
    const float* Whh = dir ? Whh_b : Whh_f;

    float acc[4][4] = {};
    for (int kt = 0; kt < Hq / 16; ++kt) {
        int k0 = kt * 16;
#pragma unroll
        for (int i = 0; i < 2; ++i) {
            int ee = threadIdx.x + i * 256;
            int r = ee >> 4, k = ee & 15;
            sH[r][k] = d_hbuf[cur][rec][b0 + r][k0 + k];
        }
#pragma unroll
        for (int i = 0; i < 8; ++i) {
            int ee = threadIdx.x + i * 256;
            int n = ee >> 4, k = ee & 15;
            int gate = n >> 5, jj = n & 31;
            sW[n][k] = Whh[(long)(gate * Hq + j0 + jj) * Hq + k0 + k];
        }
        __syncthreads();
#pragma unroll
        for (int k = 0; k < 16; ++k) {
            float a[4], w[4];
#pragma unroll
            for (int i = 0; i < 4; ++i) a[i] = sH[ty * 4 + i][k];
#pragma unroll
            for (int g = 0; g < 4; ++g) w[g] = sW[g * 32 + tx][k];
#pragma unroll
            for (int i = 0; i < 4; ++i)
#pragma unroll
                for (int g = 0; g < 4; ++g) acc[i][g] += a[i] * w[g];
        }
        __syncthreads();
    }

    int j = j0 + tx;
    const int* lens = seq ? s2_len : s1_len;
#pragma unroll
    for (int i = 0; i < 4; ++i) {
        int b = b0 + ty * 4 + i;
        int len = lens[b];
        // bwd: at step t consume reversed position idx(b,t); write h back there too
        int tpos = dir ? ((t < len) ? (len - 1 - t) : t) : t;
        long row = (long)(seq * Bq + b) * Tq + tpos;
        float gi = acc[i][0] + d_xW[dir][row][j];
        float gf = acc[i][1] + d_xW[dir][row][Hq + j];
        float gg = acc[i][2] + d_xW[dir][row][2 * Hq + j];
        float go = acc[i][3] + d_xW[dir][row][3 * Hq + j];
        float si = 1.f / (1.f + expf(-gi));
        float sf = 1.f / (1.f + expf(-gf));
        float so = 1.f / (1.f + expf(-go));
        float c  = sf * d_cbuf[rec][b][j] + si * tanhf(gg);
        float h  = so * tanhf(c);
        d_cbuf[rec][b][j]          = c;
        d_hbuf[cur ^ 1][rec][b][j] = h;
        d_Hout[row][dir * Hq + j]  = h;
    }
}

// ---------------- attention projection GEMM: P = Hout @ S1W^T ---------------
__global__ __launch_bounds__(256)
void attn_gemm(const float* __restrict__ S1W) {
    __shared__ float sA[64][17];
    __shared__ float sB[64][17];
    int tx = threadIdx.x & 15, ty = threadIdx.x >> 4;
    int n0 = blockIdx.x * 64, m0 = blockIdx.y * 64;
    float acc[4][4] = {};
    for (int kt = 0; kt < D2H / 16; ++kt) {
        int k0 = kt * 16;
#pragma unroll
        for (int i = 0; i < 4; ++i) {
            int e = threadIdx.x + i * 256;
            int r = e >> 4, k = e & 15;
            sA[r][k] = d_Hout[m0 + r][k0 + k];
            sB[r][k] = S1W[(long)(n0 + r) * D2H + k0 + k];
        }
        __syncthreads();
#pragma unroll
        for (int k = 0; k < 16; ++k) {
            float a[4], bb[4];
#pragma unroll
            for (int i = 0; i < 4; ++i) a[i] = sA[ty * 4 + i][k];
#pragma unroll
            for (int j = 0; j < 4; ++j) bb[j] = sB[tx * 4 + j][k];
#pragma unroll
            for (int i = 0; i < 4; ++i)
#pragma unroll
                for (int j = 0; j < 4; ++j) acc[i][j] += a[i] * bb[j];
        }
        __syncthreads();
    }
#pragma unroll
    for (int i = 0; i < 4; ++i)
#pragma unroll
        for (int j = 0; j < 4; ++j)
            d_P[m0 + ty * 4 + i][n0 + tx * 4 + j] = acc[i][j];
}

// ---------------- masked softmax attention pooling ---------------------------
__global__ __launch_bounds__(128)
void attn_pool(const int* __restrict__ s1_len, const int* __restrict__ s2_len,
               const float* __restrict__ S2W) {
    __shared__ float sS2[Cq];
    __shared__ float ssc[Tq];
    __shared__ float red[Tq];
    int sb = blockIdx.x;            // seq*64 + b
    int seq = sb >> 6, b = sb & 63;
    int t = threadIdx.x;
    for (int c = t; c < Cq; c += Tq) sS2[c] = S2W[c];
    __syncthreads();

    long row = (long)sb * Tq + t;
    float s = 0.f;
    for (int c = 0; c < Cq; ++c) s += tanhf(d_P[row][c]) * sS2[c];
    int len = (seq ? s2_len : s1_len)[b];
    ssc[t] = (t < len) ? s : -1e9f;
    __syncthreads();

    red[t] = ssc[t]; __syncthreads();
    for (int o = 64; o > 0; o >>= 1) { if (t < o) red[t] = fmaxf(red[t], red[t + o]); __syncthreads(); }
    float mx = red[0]; __syncthreads();
    float ex = expf(ssc[t] - mx);
    red[t] = ex; __syncthreads();
    for (int o = 64; o > 0; o >>= 1) { if (t < o) red[t] += red[t + o]; __syncthreads(); }
    float inv = 1.f / red[0];
    __syncthreads();
    ssc[t] = ex * inv;
    __syncthreads();

    long rowbase = (long)sb * Tq;
    for (int d = t; d < D2H; d += Tq) {
        float acc = 0.f;
        for (int tt = 0; tt < Tq; ++tt) acc += ssc[tt] * d_Hout[rowbase + tt][d];
        d_r[seq][b][d] = acc;
    }
}

// ---------------- final MLP head + sigmoid ----------------------------------
__global__ __launch_bounds__(512)
void final_mlp(const float* __restrict__ mlpW, const float* __restrict__ mlpb,
               const float* __restrict__ outW, const float* __restrict__ outb,
               float* __restrict__ out) {
    __shared__ float merged[4 * Hq];   // 2048
    __shared__ float smlp[Mq];
    __shared__ float red[16];
    int b = blockIdx.x;
    int tid = threadIdx.x;

    for (int d = tid; d < 2 * D2H; d += Mq) {
        float v;
        if (d < D2H) v = d_r[0][b][d] + d_r[1][b][d];
        else { float df = d_r[0][b][d - D2H] - d_r[1][b][d - D2H]; v = df * df; }
        merged[d] = v;
    }
    __syncthreads();

    int warp = tid >> 5, lane = tid & 31;
    for (int m = warp * 32; m < warp * 32 + 32; ++m) {
        float p = 0.f;
        for (int d = lane; d < 4 * Hq; d += 32) p += merged[d] * mlpW[(long)m * 4 * Hq + d];
        for (int o = 16; o > 0; o >>= 1) p += __shfl_down_sync(0xffffffff, p, o);
        if (lane == 0) smlp[m] = p + mlpb[m];
    }
    __syncthreads();

    float p = smlp[tid] * outW[tid];
    for (int o = 16; o > 0; o >>= 1) p += __shfl_down_sync(0xffffffff, p, o);
    if (lane == 0) red[warp] = p;
    __syncthreads();
    if (tid == 0) {
        float l = outb[0];
        for (int w = 0; w < 16; ++w) l += red[w];
        out[b] = 1.f / (1.f + expf(-l));
    }
}

// ---------------- launch ------------------------------------------------------
extern "C" void kernel_launch(void* const* d_in, const int* in_sizes, int n_in,
                              void* d_out, int out_size) {
    const int*   s1     = (const int*)d_in[0];
    const int*   s2     = (const int*)d_in[1];
    const int*   s1_len = (const int*)d_in[2];
    const int*   s2_len = (const int*)d_in[3];
    const float* s1_h0  = (const float*)d_in[4];
    const float* s1_c0  = (const float*)d_in[5];
    const float* s2_h0  = (const float*)d_in[6];
    const float* s2_c0  = (const float*)d_in[7];
    const float* emb    = (const float*)d_in[8];
    const float* Wih_f  = (const float*)d_in[9];
    const float* Whh_f  = (const float*)d_in[10];
    const float* b_f    = (const float*)d_in[11];
    const float* Wih_b  = (const float*)d_in[12];
    const float* Whh_b  = (const float*)d_in[13];
    const float* b_b    = (const float*)d_in[14];
    const float* S1W    = (const float*)d_in[15];
    const float* S2W    = (const float*)d_in[16];
    const float* mlpW   = (const float*)d_in[17];
    const float* mlpb   = (const float*)d_in[18];
    const float* outW   = (const float*)d_in[19];
    const float* outb   = (const float*)d_in[20];
    float* out = (float*)d_out;

    init_state<<<(4 * Bq * Hq + 255) / 256, 256>>>(s1_h0, s1_c0, s2_h0, s2_c0);

    dim3 gx(G4H / 64, NROWS / 64);   // (32, 256)
    xw_gemm<<<gx, 256>>>(s1, s2, emb, Wih_f, b_f, 0);
    xw_gemm<<<gx, 256>>>(s1, s2, emb, Wih_b, b_b, 1);

    for (int t = 0; t < Tq; ++t)
        lstm_step<<<dim3(16, 8), 256>>>(t, t & 1, s1_len, s2_len, Whh_f, Whh_b);

    attn_gemm<<<dim3(Cq / 64, NROWS / 64), 256>>>(S1W);   // (4, 256)
    attn_pool<<<128, 128>>>(s1_len, s2_len, S2W);
    final_mlp<<<Bq, 512>>>(mlpW, mlpb, outW, outb, out);
}